// round 16
// baseline (speedup 1.0000x reference)
#include <cuda_runtime.h>
#include <cuda_fp16.h>
#include <math.h>
#include <stdint.h>

// Problem constants: B=4, S=2048, D=1024, H=16, hs=64
#define BATCH 4
#define SEQ   2048
#define DIM   1024
#define HEADS 16
#define HS    64
#define W3    3072   // 3*DIM

// ---------------- helpers ----------------
__device__ __forceinline__ void mma_f16(float* d, const uint32_t* a,
                                        uint32_t b0, uint32_t b1) {
    asm("mma.sync.aligned.m16n8k16.row.col.f32.f16.f16.f32 "
        "{%0,%1,%2,%3},{%4,%5,%6,%7},{%8,%9},{%0,%1,%2,%3};"
        : "+f"(d[0]), "+f"(d[1]), "+f"(d[2]), "+f"(d[3])
        : "r"(a[0]), "r"(a[1]), "r"(a[2]), "r"(a[3]), "r"(b0), "r"(b1));
}
__device__ __forceinline__ void ldsm_x4(uint32_t* r, uint32_t addr) {
    asm volatile("ldmatrix.sync.aligned.m8n8.x4.shared.b16 {%0,%1,%2,%3}, [%4];"
                 : "=r"(r[0]), "=r"(r[1]), "=r"(r[2]), "=r"(r[3]) : "r"(addr));
}
__device__ __forceinline__ void ldsm_x4t(uint32_t* r, uint32_t addr) {
    asm volatile("ldmatrix.sync.aligned.m8n8.x4.trans.shared.b16 {%0,%1,%2,%3}, [%4];"
                 : "=r"(r[0]), "=r"(r[1]), "=r"(r[2]), "=r"(r[3]) : "r"(addr));
}
__device__ __forceinline__ void cpa16(uint32_t dst, const void* src) {
    asm volatile("cp.async.cg.shared.global [%0], [%1], 16;" :: "r"(dst), "l"(src));
}
__device__ __forceinline__ void cp_commit() {
    asm volatile("cp.async.commit_group;");
}
template<int N>
__device__ __forceinline__ void cp_wait() {
    asm volatile("cp.async.wait_group %0;" :: "n"(N));
}
__device__ __forceinline__ float fex2(float x) {
    float r;
    asm("ex2.approx.f32 %0, %1;" : "=f"(r) : "f"(x));
    return r;
}
__device__ __forceinline__ uint32_t packh2(float a, float b) {
    __half2 h = __float22half2_rn(make_float2(a, b));
    return *(uint32_t*)&h;
}
__device__ __forceinline__ uint32_t ex2h2(uint32_t x) {
    uint32_t r;
    asm("ex2.approx.f16x2 %0, %1;" : "=r"(r) : "r"(x));
    return r;
}
#define ONES_H2 0x3C003C00u

// ---------------- scratch (device globals) ----------------
__device__ __half g_qkv[(size_t)BATCH * SEQ * W3];
__device__ __half g_ctx[(size_t)BATCH * SEQ * DIM];
__device__ __half g_enc_h[(size_t)BATCH * SEQ * DIM];
__device__ __half g_wattn_h[(size_t)DIM * W3];
__device__ __half g_wproj_h[(size_t)DIM * DIM];

// ---------------- fp32 -> fp16, all three tensors in one launch ----------------
#define CVT_N1 ((BATCH * SEQ * DIM) / 4)
#define CVT_N2 ((DIM * W3) / 4)
#define CVT_N3 ((DIM * DIM) / 4)
#define CVT_TOTAL (CVT_N1 + CVT_N2 + CVT_N3)

__global__ void __launch_bounds__(256) cvt_all_kernel(
    const float4* __restrict__ enc, const float4* __restrict__ wa,
    const float4* __restrict__ wp,
    uint2* __restrict__ enc_o, uint2* __restrict__ wa_o, uint2* __restrict__ wp_o)
{
    int i = blockIdx.x * 256 + threadIdx.x;
    if (i >= CVT_TOTAL) return;
    const float4* src;
    uint2* dst;
    int j;
    if (i < CVT_N1)                { src = enc; dst = enc_o; j = i; }
    else if (i < CVT_N1 + CVT_N2)  { src = wa;  dst = wa_o;  j = i - CVT_N1; }
    else                           { src = wp;  dst = wp_o;  j = i - CVT_N1 - CVT_N2; }
    float4 v = src[j];
    uint2 u;
    u.x = packh2(v.x, v.y);
    u.y = packh2(v.z, v.w);
    dst[j] = u;
}

// ---------------------------------------------------------------------------
// fp16 tensor-core GEMM (frozen best config):
// C[M,N] = A[M,K] @ B[K,N] + bias[N]; CTA 128x128x64, 2-stage cp.async.
// ---------------------------------------------------------------------------
#define GAS 72
#define GBS 136
#define GASZ (128 * GAS)
#define GBSZ (64 * GBS)
#define GEMM_SMEM (2 * (GASZ + GBSZ) * 2)   // 71680 B

__global__ void __launch_bounds__(256) f16_gemm(
    const __half* __restrict__ A, const __half* __restrict__ B,
    const float* __restrict__ bias, void* __restrict__ Cv,
    int M, int N, int K, int half_out)
{
    extern __shared__ __half smh[];
    __half* As = smh;
    __half* Bs = smh + 2 * GASZ;

    const int tid = threadIdx.x, lane = tid & 31, w = tid >> 5;
    const int wm = w >> 2, wn = w & 3, g = lane >> 2, tg = lane & 3;
    const int bm = blockIdx.y * 128, bn = blockIdx.x * 128;

    const uint32_t as_smem = (uint32_t)__cvta_generic_to_shared(As);
    const uint32_t bs_smem = (uint32_t)__cvta_generic_to_shared(Bs);

    float acc[4][4][4];
#pragma unroll
    for (int mt = 0; mt < 4; mt++)
#pragma unroll
        for (int nt = 0; nt < 4; nt++)
#pragma unroll
            for (int c = 0; c < 4; c++) acc[mt][nt][c] = 0.0f;

    const uint32_t a_base = as_smem +
        (uint32_t)(((wm * 64 + (lane & 15)) * GAS + (lane >> 4) * 8) * 2);
    const int b_krow = (lane & 15);
    const int b_noff = (lane >> 4) * 8;

    auto issue = [&](int i, int s) {
        const __half* Ag = A + (size_t)bm * K + i * 64;
        const uint32_t sa = as_smem + (uint32_t)(s * GASZ * 2);
#pragma unroll
        for (int t = 0; t < 4; t++) {
            int c = tid + t * 256, r = c >> 3, q = c & 7;
            cpa16(sa + (uint32_t)((r * GAS + q * 8) * 2), Ag + (size_t)r * K + q * 8);
        }
        const __half* Bg = B + (size_t)i * 64 * N + bn;
        const uint32_t sb = bs_smem + (uint32_t)(s * GBSZ * 2);
#pragma unroll
        for (int t = 0; t < 4; t++) {
            int c = tid + t * 256, r = c >> 4, u = c & 15;
            cpa16(sb + (uint32_t)((r * GBS + u * 8) * 2), Bg + (size_t)r * N + u * 8);
        }
    };

    const int nkt = K / 64;
    issue(0, 0); cp_commit();

    for (int i = 0; i < nkt; i++) {
        cp_wait<0>();
        __syncthreads();
        if (i + 1 < nkt) { issue(i + 1, (i + 1) & 1); cp_commit(); }

        const int s = i & 1;
        const uint32_t a0 = a_base + (uint32_t)(s * GASZ * 2);
        const uint32_t b0s = bs_smem + (uint32_t)(s * GBSZ * 2);

#pragma unroll
        for (int ks = 0; ks < 4; ks++) {
            uint32_t afr[4][4];
#pragma unroll
            for (int mt = 0; mt < 4; mt++)
                ldsm_x4(afr[mt], a0 + (uint32_t)((mt * 16 * GAS + ks * 16) * 2));
#pragma unroll
            for (int np = 0; np < 2; np++) {
                uint32_t bb[4];
                uint32_t baddr = b0s + (uint32_t)(
                    ((ks * 16 + b_krow) * GBS + wn * 32 + np * 16 + b_noff) * 2);
                ldsm_x4t(bb, baddr);
#pragma unroll
                for (int mt = 0; mt < 4; mt++) {
                    mma_f16(acc[mt][2 * np],     afr[mt], bb[0], bb[1]);
                    mma_f16(acc[mt][2 * np + 1], afr[mt], bb[2], bb[3]);
                }
            }
        }
    }

    // ---- epilogue ----
#pragma unroll
    for (int mt = 0; mt < 4; mt++) {
#pragma unroll
        for (int nt = 0; nt < 4; nt++) {
            int row = bm + wm * 64 + mt * 16 + g;
            int col = bn + wn * 32 + nt * 8 + 2 * tg;
            float b0 = bias[col], b1 = bias[col + 1];
            float v00 = acc[mt][nt][0] + b0, v01 = acc[mt][nt][1] + b1;
            float v10 = acc[mt][nt][2] + b0, v11 = acc[mt][nt][3] + b1;
            if (half_out) {
                __half* C = (__half*)Cv;
                *(__half2*)(C + (size_t)row * N + col) =
                    __float22half2_rn(make_float2(v00, v01));
                *(__half2*)(C + (size_t)(row + 8) * N + col) =
                    __float22half2_rn(make_float2(v10, v11));
            } else {
                float* C = (float*)Cv;
                *(float2*)(C + (size_t)row * N + col)       = make_float2(v00, v01);
                *(float2*)(C + (size_t)(row + 8) * N + col) = make_float2(v10, v11);
            }
        }
    }
}

// ---------------------------------------------------------------------------
// fp16 tensor-core flash attention (causal). BQ=128, BK=128, 8 warps x 16 rows.
// Q frags + P in registers; f16x2 exp; row sums via mma vs all-ones.
// FMA-fused softmax scaling (max over raw S, scale folded into the fused
// multiply-subtract). Warp-uniform skipping of fully-masked 16-key chunks in
// the diagonal tile (QK, softmax, PV, row-sum all bounded by ntp <= w).
// 2-stage cp.async K/V; exp2 domain.
// ---------------------------------------------------------------------------
#define AST 72
#define QSZ (128 * AST)
#define KVSZ (128 * AST)
#define ATTN_SMEM ((QSZ + 4 * KVSZ) * 2)   // 92160 B
#define SCALE_L2E 0.18033688f  // (1/8) * log2(e)

__global__ void __launch_bounds__(256) attn_f16_kernel(
    const __half* __restrict__ qkv, __half* __restrict__ ctx)
{
    extern __shared__ __half smh[];
    __half* Qs = smh;
    __half* Ks = smh + QSZ;
    __half* Vs = Ks + 2 * KVSZ;

    const int qt = (int)gridDim.x - 1 - (int)blockIdx.x;   // heavy tiles first
    const int bh = blockIdx.y;
    const int b = bh >> 4, h = bh & 15;
    const int qb = qt * 128;

    const __half* base = qkv + (size_t)b * SEQ * W3;
    const __half* qptr = base + h * HS;
    const __half* kptr = base + DIM + h * HS;
    const __half* vptr = base + 2 * DIM + h * HS;

    const int tid = threadIdx.x, lane = tid & 31, w = tid >> 5;
    const int g = lane >> 2, tg = lane & 3;

    const uint32_t q_smem = (uint32_t)__cvta_generic_to_shared(Qs);
    const uint32_t k_smem = (uint32_t)__cvta_generic_to_shared(Ks);
    const uint32_t v_smem = (uint32_t)__cvta_generic_to_shared(Vs);

#pragma unroll
    for (int t = 0; t < 4; t++) {
        int c = tid + t * 256, r = c >> 3, u = c & 7;
        cpa16(q_smem + (uint32_t)((r * AST + u * 8) * 2),
              qptr + (size_t)(qb + r) * W3 + u * 8);
    }

    auto issue_kv = [&](int kt, int s) {
        const size_t rowb = (size_t)kt * 128 * W3;
        const uint32_t ks_ = k_smem + (uint32_t)(s * KVSZ * 2);
        const uint32_t vs_ = v_smem + (uint32_t)(s * KVSZ * 2);
#pragma unroll
        for (int t = 0; t < 4; t++) {
            int c = tid + t * 256, r = c >> 3, u = c & 7;
            cpa16(ks_ + (uint32_t)((r * AST + u * 8) * 2),
                  kptr + rowb + (size_t)r * W3 + u * 8);
            cpa16(vs_ + (uint32_t)((r * AST + u * 8) * 2),
                  vptr + rowb + (size_t)r * W3 + u * 8);
        }
    };

    issue_kv(0, 0); cp_commit();
    cp_wait<0>();
    __syncthreads();

    const uint32_t q_base = q_smem +
        (uint32_t)(((w * 16 + (lane & 15)) * AST + (lane >> 4) * 8) * 2);
    uint32_t qfr[4][4];
#pragma unroll
    for (int ks = 0; ks < 4; ks++)
        ldsm_x4(qfr[ks], q_base + ks * 32);

    float m0 = -1e30f, m1 = -1e30f;
    float o[8][4];
#pragma unroll
    for (int nt = 0; nt < 8; nt++)
#pragma unroll
        for (int c = 0; c < 4; c++) o[nt][c] = 0.0f;
    float osum[4] = {0.0f, 0.0f, 0.0f, 0.0f};

    const int nkt = qt + 1;
    const int qr0 = qb + w * 16 + g;

    const int kb_row = ((lane >> 3) & 1) * 8 + (lane & 7);
    const int kb_u   = (lane >> 4) * 8;
    const int vb_row = (lane & 15);
    const int vb_u   = (lane >> 4) * 8;

    for (int kt = 0; kt < nkt; kt++) {
        const int kt0 = kt * 128;
        cp_wait<0>();
        __syncthreads();
        if (kt + 1 < nkt) issue_kv(kt + 1, (kt + 1) & 1);
        cp_commit();

        const int s = kt & 1;
        const uint32_t ksb = k_smem + (uint32_t)(s * KVSZ * 2);
        const uint32_t vsb = v_smem + (uint32_t)(s * KVSZ * 2);

        // Warp-uniform chunk bound: on the diagonal tile, 16-key chunk c is
        // fully masked for this warp iff kt0 + c*16 > qb + w*16 + 15 <=> c > w.
        const bool diag = (kt == qt);
        const int cmax = diag ? (w + 1) : 8;     // live 16-key chunks
        const int ntmax = 2 * cmax;              // live 8-key accum tiles

        // ---- S = Q K^T (raw, unscaled) ----
        float sc[16][4];
#pragma unroll
        for (int nt = 0; nt < 16; nt++)
#pragma unroll
            for (int c = 0; c < 4; c++) sc[nt][c] = 0.0f;

#pragma unroll
        for (int ks = 0; ks < 4; ks++) {
#pragma unroll
            for (int ntp = 0; ntp < 8; ntp++) {
                if (ntp < cmax) {
                    uint32_t bb[4];
                    ldsm_x4(bb, ksb + (uint32_t)(
                        ((ntp * 16 + kb_row) * AST + ks * 16 + kb_u) * 2));
                    mma_f16(sc[2 * ntp],     qfr[ks], bb[0], bb[2]);
                    mma_f16(sc[2 * ntp + 1], qfr[ks], bb[1], bb[3]);
                }
            }
        }

        // ---- causal mask (diagonal tile; raw domain) ----
        if (diag) {
#pragma unroll
            for (int nt = 0; nt < 16; nt++) {
                if (nt < ntmax) {
                    int kc = kt0 + nt * 8 + 2 * tg;
                    if (qr0 < kc)         sc[nt][0] = -1e30f;
                    if (qr0 < kc + 1)     sc[nt][1] = -1e30f;
                    if (qr0 + 8 < kc)     sc[nt][2] = -1e30f;
                    if (qr0 + 8 < kc + 1) sc[nt][3] = -1e30f;
                }
            }
        }

        // ---- online softmax (base-2): max over raw, FMA-fused scale+sub ----
        float mx0 = -1e30f, mx1 = -1e30f;
#pragma unroll
        for (int nt = 0; nt < 16; nt++) {
            if (nt < ntmax) {
                mx0 = fmaxf(mx0, fmaxf(sc[nt][0], sc[nt][1]));
                mx1 = fmaxf(mx1, fmaxf(sc[nt][2], sc[nt][3]));
            }
        }
        mx0 = fmaxf(mx0, __shfl_xor_sync(0xffffffffu, mx0, 1));
        mx0 = fmaxf(mx0, __shfl_xor_sync(0xffffffffu, mx0, 2));
        mx1 = fmaxf(mx1, __shfl_xor_sync(0xffffffffu, mx1, 1));
        mx1 = fmaxf(mx1, __shfl_xor_sync(0xffffffffu, mx1, 2));

        float mn0 = fmaxf(m0, mx0 * SCALE_L2E);
        float mn1 = fmaxf(m1, mx1 * SCALE_L2E);
        float al0 = fex2(m0 - mn0), al1 = fex2(m1 - mn1);
        m0 = mn0; m1 = mn1;

        uint32_t pfr[8][4];
#pragma unroll
        for (int nt = 0; nt < 16; nt++) {
            if (nt < ntmax) {
                pfr[nt >> 1][(nt & 1) * 2 + 0] = ex2h2(packh2(
                    fmaf(sc[nt][0], SCALE_L2E, -mn0),
                    fmaf(sc[nt][1], SCALE_L2E, -mn0)));
                pfr[nt >> 1][(nt & 1) * 2 + 1] = ex2h2(packh2(
                    fmaf(sc[nt][2], SCALE_L2E, -mn1),
                    fmaf(sc[nt][3], SCALE_L2E, -mn1)));
            }
        }

#pragma unroll
        for (int nt = 0; nt < 8; nt++) {
            o[nt][0] *= al0; o[nt][1] *= al0;
            o[nt][2] *= al1; o[nt][3] *= al1;
        }
        osum[0] *= al0; osum[1] *= al0;
        osum[2] *= al1; osum[3] *= al1;

        // ---- O += P @ V; row sums += P @ ones (skip dead chunks) ----
#pragma unroll
        for (int ks2 = 0; ks2 < 8; ks2++) {
            if (ks2 < cmax) {
#pragma unroll
                for (int ct = 0; ct < 4; ct++) {
                    uint32_t bb[4];
                    ldsm_x4t(bb, vsb + (uint32_t)(
                        ((ks2 * 16 + vb_row) * AST + ct * 16 + vb_u) * 2));
                    mma_f16(o[2 * ct],     pfr[ks2], bb[0], bb[1]);
                    mma_f16(o[2 * ct + 1], pfr[ks2], bb[2], bb[3]);
                }
                mma_f16(osum, pfr[ks2], ONES_H2, ONES_H2);
            }
        }
    }

    // ---- epilogue: ctx fp16 ----
    float inv0 = 1.0f / osum[0], inv1 = 1.0f / osum[2];
    __half* orow0 = ctx + ((size_t)b * SEQ + qr0) * DIM + h * HS;
    __half* orow1 = orow0 + (size_t)8 * DIM;
#pragma unroll
    for (int nt = 0; nt < 8; nt++) {
        int col = nt * 8 + 2 * tg;
        *(__half2*)(orow0 + col) =
            __float22half2_rn(make_float2(o[nt][0] * inv0, o[nt][1] * inv0));
        *(__half2*)(orow1 + col) =
            __float22half2_rn(make_float2(o[nt][2] * inv1, o[nt][3] * inv1));
    }
}

// ---------------------------------------------------------------------------
extern "C" void kernel_launch(void* const* d_in, const int* in_sizes, int n_in,
                              void* d_out, int out_size)
{
    const float* enc    = (const float*)d_in[0];
    const float* w_attn = (const float*)d_in[1];
    const float* b_attn = (const float*)d_in[2];
    const float* w_proj = (const float*)d_in[3];
    const float* b_proj = (const float*)d_in[4];
    float* out = (float*)d_out;

    __half *qkv = nullptr, *ctx = nullptr, *enc_h = nullptr,
           *wattn_h = nullptr, *wproj_h = nullptr;
    cudaGetSymbolAddress((void**)&qkv,     g_qkv);
    cudaGetSymbolAddress((void**)&ctx,     g_ctx);
    cudaGetSymbolAddress((void**)&enc_h,   g_enc_h);
    cudaGetSymbolAddress((void**)&wattn_h, g_wattn_h);
    cudaGetSymbolAddress((void**)&wproj_h, g_wproj_h);

    const int M = BATCH * SEQ;   // 8192

    // ---- pre-convert fp32 -> fp16 (single launch) ----
    cvt_all_kernel<<<(CVT_TOTAL + 255) / 256, 256>>>(
        (const float4*)enc, (const float4*)w_attn, (const float4*)w_proj,
        (uint2*)enc_h, (uint2*)wattn_h, (uint2*)wproj_h);

    cudaFuncSetAttribute(f16_gemm,
                         cudaFuncAttributeMaxDynamicSharedMemorySize, GEMM_SMEM);
    cudaFuncSetAttribute(attn_f16_kernel,
                         cudaFuncAttributeMaxDynamicSharedMemorySize, ATTN_SMEM);

    // ---- QKV GEMM (fp16 out) ----
    {
        dim3 grid(W3 / 128, M / 128);
        f16_gemm<<<grid, 256, GEMM_SMEM>>>(enc_h, wattn_h, b_attn, qkv,
                                           M, W3, DIM, 1);
    }

    // ---- Attention ----
    {
        dim3 grid(SEQ / 128, BATCH * HEADS);
        attn_f16_kernel<<<grid, 256, ATTN_SMEM>>>(qkv, ctx);
    }

    // ---- Output projection (fp32 out) ----
    {
        dim3 grid(DIM / 128, M / 128);
        f16_gemm<<<grid, 256, GEMM_SMEM>>>(ctx, wproj_h, b_proj, out,
                                           M, DIM, DIM, 0);
    }
}

// round 17
// speedup vs baseline: 1.1037x; 1.1037x over previous
#include <cuda_runtime.h>
#include <cuda_fp16.h>
#include <math.h>
#include <stdint.h>

// Problem constants: B=4, S=2048, D=1024, H=16, hs=64
#define BATCH 4
#define SEQ   2048
#define DIM   1024
#define HEADS 16
#define HS    64
#define W3    3072   // 3*DIM

// ---------------- helpers ----------------
__device__ __forceinline__ void mma_f16(float* d, const uint32_t* a,
                                        uint32_t b0, uint32_t b1) {
    asm("mma.sync.aligned.m16n8k16.row.col.f32.f16.f16.f32 "
        "{%0,%1,%2,%3},{%4,%5,%6,%7},{%8,%9},{%0,%1,%2,%3};"
        : "+f"(d[0]), "+f"(d[1]), "+f"(d[2]), "+f"(d[3])
        : "r"(a[0]), "r"(a[1]), "r"(a[2]), "r"(a[3]), "r"(b0), "r"(b1));
}
__device__ __forceinline__ void ldsm_x4(uint32_t* r, uint32_t addr) {
    asm volatile("ldmatrix.sync.aligned.m8n8.x4.shared.b16 {%0,%1,%2,%3}, [%4];"
                 : "=r"(r[0]), "=r"(r[1]), "=r"(r[2]), "=r"(r[3]) : "r"(addr));
}
__device__ __forceinline__ void ldsm_x4t(uint32_t* r, uint32_t addr) {
    asm volatile("ldmatrix.sync.aligned.m8n8.x4.trans.shared.b16 {%0,%1,%2,%3}, [%4];"
                 : "=r"(r[0]), "=r"(r[1]), "=r"(r[2]), "=r"(r[3]) : "r"(addr));
}
__device__ __forceinline__ void cpa16(uint32_t dst, const void* src) {
    asm volatile("cp.async.cg.shared.global [%0], [%1], 16;" :: "r"(dst), "l"(src));
}
__device__ __forceinline__ void cp_commit() {
    asm volatile("cp.async.commit_group;");
}
template<int N>
__device__ __forceinline__ void cp_wait() {
    asm volatile("cp.async.wait_group %0;" :: "n"(N));
}
__device__ __forceinline__ float fex2(float x) {
    float r;
    asm("ex2.approx.f32 %0, %1;" : "=f"(r) : "f"(x));
    return r;
}
__device__ __forceinline__ uint32_t packh2(float a, float b) {
    __half2 h = __float22half2_rn(make_float2(a, b));
    return *(uint32_t*)&h;
}
__device__ __forceinline__ uint32_t ex2h2(uint32_t x) {
    uint32_t r;
    asm("ex2.approx.f16x2 %0, %1;" : "=r"(r) : "r"(x));
    return r;
}
#define ONES_H2 0x3C003C00u

// ---------------- scratch (device globals) ----------------
__device__ __half g_qkv[(size_t)BATCH * SEQ * W3];
__device__ __half g_ctx[(size_t)BATCH * SEQ * DIM];
__device__ __half g_enc_h[(size_t)BATCH * SEQ * DIM];
__device__ __half g_wattn_h[(size_t)DIM * W3];
__device__ __half g_wproj_h[(size_t)DIM * DIM];

// ---------------- fp32 -> fp16, all three tensors in one launch ----------------
#define CVT_N1 ((BATCH * SEQ * DIM) / 4)
#define CVT_N2 ((DIM * W3) / 4)
#define CVT_N3 ((DIM * DIM) / 4)
#define CVT_TOTAL (CVT_N1 + CVT_N2 + CVT_N3)

__global__ void __launch_bounds__(256) cvt_all_kernel(
    const float4* __restrict__ enc, const float4* __restrict__ wa,
    const float4* __restrict__ wp,
    uint2* __restrict__ enc_o, uint2* __restrict__ wa_o, uint2* __restrict__ wp_o)
{
    int i = blockIdx.x * 256 + threadIdx.x;
    if (i >= CVT_TOTAL) return;
    const float4* src;
    uint2* dst;
    int j;
    if (i < CVT_N1)                { src = enc; dst = enc_o; j = i; }
    else if (i < CVT_N1 + CVT_N2)  { src = wa;  dst = wa_o;  j = i - CVT_N1; }
    else                           { src = wp;  dst = wp_o;  j = i - CVT_N1 - CVT_N2; }
    float4 v = src[j];
    uint2 u;
    u.x = packh2(v.x, v.y);
    u.y = packh2(v.z, v.w);
    dst[j] = u;
}

// ---------------------------------------------------------------------------
// fp16 tensor-core GEMM (frozen best config):
// C[M,N] = A[M,K] @ B[K,N] + bias[N]; CTA 128x128x64, 2-stage cp.async.
// ---------------------------------------------------------------------------
#define GAS 72
#define GBS 136
#define GASZ (128 * GAS)
#define GBSZ (64 * GBS)
#define GEMM_SMEM (2 * (GASZ + GBSZ) * 2)   // 71680 B

__global__ void __launch_bounds__(256) f16_gemm(
    const __half* __restrict__ A, const __half* __restrict__ B,
    const float* __restrict__ bias, void* __restrict__ Cv,
    int M, int N, int K, int half_out)
{
    extern __shared__ __half smh[];
    __half* As = smh;
    __half* Bs = smh + 2 * GASZ;

    const int tid = threadIdx.x, lane = tid & 31, w = tid >> 5;
    const int wm = w >> 2, wn = w & 3, g = lane >> 2, tg = lane & 3;
    const int bm = blockIdx.y * 128, bn = blockIdx.x * 128;

    const uint32_t as_smem = (uint32_t)__cvta_generic_to_shared(As);
    const uint32_t bs_smem = (uint32_t)__cvta_generic_to_shared(Bs);

    float acc[4][4][4];
#pragma unroll
    for (int mt = 0; mt < 4; mt++)
#pragma unroll
        for (int nt = 0; nt < 4; nt++)
#pragma unroll
            for (int c = 0; c < 4; c++) acc[mt][nt][c] = 0.0f;

    const uint32_t a_base = as_smem +
        (uint32_t)(((wm * 64 + (lane & 15)) * GAS + (lane >> 4) * 8) * 2);
    const int b_krow = (lane & 15);
    const int b_noff = (lane >> 4) * 8;

    auto issue = [&](int i, int s) {
        const __half* Ag = A + (size_t)bm * K + i * 64;
        const uint32_t sa = as_smem + (uint32_t)(s * GASZ * 2);
#pragma unroll
        for (int t = 0; t < 4; t++) {
            int c = tid + t * 256, r = c >> 3, q = c & 7;
            cpa16(sa + (uint32_t)((r * GAS + q * 8) * 2), Ag + (size_t)r * K + q * 8);
        }
        const __half* Bg = B + (size_t)i * 64 * N + bn;
        const uint32_t sb = bs_smem + (uint32_t)(s * GBSZ * 2);
#pragma unroll
        for (int t = 0; t < 4; t++) {
            int c = tid + t * 256, r = c >> 4, u = c & 15;
            cpa16(sb + (uint32_t)((r * GBS + u * 8) * 2), Bg + (size_t)r * N + u * 8);
        }
    };

    const int nkt = K / 64;
    issue(0, 0); cp_commit();

    for (int i = 0; i < nkt; i++) {
        cp_wait<0>();
        __syncthreads();
        if (i + 1 < nkt) { issue(i + 1, (i + 1) & 1); cp_commit(); }

        const int s = i & 1;
        const uint32_t a0 = a_base + (uint32_t)(s * GASZ * 2);
        const uint32_t b0s = bs_smem + (uint32_t)(s * GBSZ * 2);

#pragma unroll
        for (int ks = 0; ks < 4; ks++) {
            uint32_t afr[4][4];
#pragma unroll
            for (int mt = 0; mt < 4; mt++)
                ldsm_x4(afr[mt], a0 + (uint32_t)((mt * 16 * GAS + ks * 16) * 2));
#pragma unroll
            for (int np = 0; np < 2; np++) {
                uint32_t bb[4];
                uint32_t baddr = b0s + (uint32_t)(
                    ((ks * 16 + b_krow) * GBS + wn * 32 + np * 16 + b_noff) * 2);
                ldsm_x4t(bb, baddr);
#pragma unroll
                for (int mt = 0; mt < 4; mt++) {
                    mma_f16(acc[mt][2 * np],     afr[mt], bb[0], bb[1]);
                    mma_f16(acc[mt][2 * np + 1], afr[mt], bb[2], bb[3]);
                }
            }
        }
    }

    // ---- epilogue ----
#pragma unroll
    for (int mt = 0; mt < 4; mt++) {
#pragma unroll
        for (int nt = 0; nt < 4; nt++) {
            int row = bm + wm * 64 + mt * 16 + g;
            int col = bn + wn * 32 + nt * 8 + 2 * tg;
            float b0 = bias[col], b1 = bias[col + 1];
            float v00 = acc[mt][nt][0] + b0, v01 = acc[mt][nt][1] + b1;
            float v10 = acc[mt][nt][2] + b0, v11 = acc[mt][nt][3] + b1;
            if (half_out) {
                __half* C = (__half*)Cv;
                *(__half2*)(C + (size_t)row * N + col) =
                    __float22half2_rn(make_float2(v00, v01));
                *(__half2*)(C + (size_t)(row + 8) * N + col) =
                    __float22half2_rn(make_float2(v10, v11));
            } else {
                float* C = (float*)Cv;
                *(float2*)(C + (size_t)row * N + col)       = make_float2(v00, v01);
                *(float2*)(C + (size_t)(row + 8) * N + col) = make_float2(v10, v11);
            }
        }
    }
}

// ---------------------------------------------------------------------------
// fp16 tensor-core flash attention (causal). BQ=128, BK=128, 8 warps x 16 rows.
// EXACT R14 structure (unconditional unrolled loops), plus FMA-fused softmax
// scaling: row max over raw S, exp argument = fmaf(sc, SCALE_L2E, -mn).
// Q frags + P in registers; f16x2 exp; row sums via mma vs all-ones.
// 2-stage cp.async K/V; exp2 domain.
// ---------------------------------------------------------------------------
#define AST 72
#define QSZ (128 * AST)
#define KVSZ (128 * AST)
#define ATTN_SMEM ((QSZ + 4 * KVSZ) * 2)   // 92160 B
#define SCALE_L2E 0.18033688f  // (1/8) * log2(e)

__global__ void __launch_bounds__(256) attn_f16_kernel(
    const __half* __restrict__ qkv, __half* __restrict__ ctx)
{
    extern __shared__ __half smh[];
    __half* Qs = smh;
    __half* Ks = smh + QSZ;
    __half* Vs = Ks + 2 * KVSZ;

    const int qt = (int)gridDim.x - 1 - (int)blockIdx.x;   // heavy tiles first
    const int bh = blockIdx.y;
    const int b = bh >> 4, h = bh & 15;
    const int qb = qt * 128;

    const __half* base = qkv + (size_t)b * SEQ * W3;
    const __half* qptr = base + h * HS;
    const __half* kptr = base + DIM + h * HS;
    const __half* vptr = base + 2 * DIM + h * HS;

    const int tid = threadIdx.x, lane = tid & 31, w = tid >> 5;
    const int g = lane >> 2, tg = lane & 3;

    const uint32_t q_smem = (uint32_t)__cvta_generic_to_shared(Qs);
    const uint32_t k_smem = (uint32_t)__cvta_generic_to_shared(Ks);
    const uint32_t v_smem = (uint32_t)__cvta_generic_to_shared(Vs);

#pragma unroll
    for (int t = 0; t < 4; t++) {
        int c = tid + t * 256, r = c >> 3, u = c & 7;
        cpa16(q_smem + (uint32_t)((r * AST + u * 8) * 2),
              qptr + (size_t)(qb + r) * W3 + u * 8);
    }

    auto issue_kv = [&](int kt, int s) {
        const size_t rowb = (size_t)kt * 128 * W3;
        const uint32_t ks_ = k_smem + (uint32_t)(s * KVSZ * 2);
        const uint32_t vs_ = v_smem + (uint32_t)(s * KVSZ * 2);
#pragma unroll
        for (int t = 0; t < 4; t++) {
            int c = tid + t * 256, r = c >> 3, u = c & 7;
            cpa16(ks_ + (uint32_t)((r * AST + u * 8) * 2),
                  kptr + rowb + (size_t)r * W3 + u * 8);
            cpa16(vs_ + (uint32_t)((r * AST + u * 8) * 2),
                  vptr + rowb + (size_t)r * W3 + u * 8);
        }
    };

    issue_kv(0, 0); cp_commit();
    cp_wait<0>();
    __syncthreads();

    const uint32_t q_base = q_smem +
        (uint32_t)(((w * 16 + (lane & 15)) * AST + (lane >> 4) * 8) * 2);
    uint32_t qfr[4][4];
#pragma unroll
    for (int ks = 0; ks < 4; ks++)
        ldsm_x4(qfr[ks], q_base + ks * 32);

    float m0 = -1e30f, m1 = -1e30f;
    float o[8][4];
#pragma unroll
    for (int nt = 0; nt < 8; nt++)
#pragma unroll
        for (int c = 0; c < 4; c++) o[nt][c] = 0.0f;
    float osum[4] = {0.0f, 0.0f, 0.0f, 0.0f};

    const int nkt = qt + 1;
    const int qr0 = qb + w * 16 + g;

    const int kb_row = ((lane >> 3) & 1) * 8 + (lane & 7);
    const int kb_u   = (lane >> 4) * 8;
    const int vb_row = (lane & 15);
    const int vb_u   = (lane >> 4) * 8;

    for (int kt = 0; kt < nkt; kt++) {
        const int kt0 = kt * 128;
        cp_wait<0>();
        __syncthreads();
        if (kt + 1 < nkt) issue_kv(kt + 1, (kt + 1) & 1);
        cp_commit();

        const int s = kt & 1;
        const uint32_t ksb = k_smem + (uint32_t)(s * KVSZ * 2);
        const uint32_t vsb = v_smem + (uint32_t)(s * KVSZ * 2);

        // ---- S = Q K^T (raw, unscaled) ----
        float sc[16][4];
#pragma unroll
        for (int nt = 0; nt < 16; nt++)
#pragma unroll
            for (int c = 0; c < 4; c++) sc[nt][c] = 0.0f;

#pragma unroll
        for (int ks = 0; ks < 4; ks++) {
#pragma unroll
            for (int ntp = 0; ntp < 8; ntp++) {
                uint32_t bb[4];
                ldsm_x4(bb, ksb + (uint32_t)(
                    ((ntp * 16 + kb_row) * AST + ks * 16 + kb_u) * 2));
                mma_f16(sc[2 * ntp],     qfr[ks], bb[0], bb[2]);
                mma_f16(sc[2 * ntp + 1], qfr[ks], bb[1], bb[3]);
            }
        }

        // ---- causal mask (diagonal tile; raw domain) ----
        if (kt0 + 128 > qb) {
#pragma unroll
            for (int nt = 0; nt < 16; nt++) {
                int kc = kt0 + nt * 8 + 2 * tg;
                if (qr0 < kc)         sc[nt][0] = -1e30f;
                if (qr0 < kc + 1)     sc[nt][1] = -1e30f;
                if (qr0 + 8 < kc)     sc[nt][2] = -1e30f;
                if (qr0 + 8 < kc + 1) sc[nt][3] = -1e30f;
            }
        }

        // ---- online softmax (base-2): max over raw, FMA-fused scale+sub ----
        float mx0 = -1e30f, mx1 = -1e30f;
#pragma unroll
        for (int nt = 0; nt < 16; nt++) {
            mx0 = fmaxf(mx0, fmaxf(sc[nt][0], sc[nt][1]));
            mx1 = fmaxf(mx1, fmaxf(sc[nt][2], sc[nt][3]));
        }
        mx0 = fmaxf(mx0, __shfl_xor_sync(0xffffffffu, mx0, 1));
        mx0 = fmaxf(mx0, __shfl_xor_sync(0xffffffffu, mx0, 2));
        mx1 = fmaxf(mx1, __shfl_xor_sync(0xffffffffu, mx1, 1));
        mx1 = fmaxf(mx1, __shfl_xor_sync(0xffffffffu, mx1, 2));

        float mn0 = fmaxf(m0, mx0 * SCALE_L2E);
        float mn1 = fmaxf(m1, mx1 * SCALE_L2E);
        float al0 = fex2(m0 - mn0), al1 = fex2(m1 - mn1);
        m0 = mn0; m1 = mn1;

        uint32_t pfr[8][4];
#pragma unroll
        for (int nt = 0; nt < 16; nt++) {
            pfr[nt >> 1][(nt & 1) * 2 + 0] = ex2h2(packh2(
                fmaf(sc[nt][0], SCALE_L2E, -mn0),
                fmaf(sc[nt][1], SCALE_L2E, -mn0)));
            pfr[nt >> 1][(nt & 1) * 2 + 1] = ex2h2(packh2(
                fmaf(sc[nt][2], SCALE_L2E, -mn1),
                fmaf(sc[nt][3], SCALE_L2E, -mn1)));
        }

#pragma unroll
        for (int nt = 0; nt < 8; nt++) {
            o[nt][0] *= al0; o[nt][1] *= al0;
            o[nt][2] *= al1; o[nt][3] *= al1;
        }
        osum[0] *= al0; osum[1] *= al0;
        osum[2] *= al1; osum[3] *= al1;

        // ---- O += P @ V; row sums += P @ ones ----
#pragma unroll
        for (int ks2 = 0; ks2 < 8; ks2++) {
#pragma unroll
            for (int ct = 0; ct < 4; ct++) {
                uint32_t bb[4];
                ldsm_x4t(bb, vsb + (uint32_t)(
                    ((ks2 * 16 + vb_row) * AST + ct * 16 + vb_u) * 2));
                mma_f16(o[2 * ct],     pfr[ks2], bb[0], bb[1]);
                mma_f16(o[2 * ct + 1], pfr[ks2], bb[2], bb[3]);
            }
            mma_f16(osum, pfr[ks2], ONES_H2, ONES_H2);
        }
    }

    // ---- epilogue: ctx fp16 ----
    float inv0 = 1.0f / osum[0], inv1 = 1.0f / osum[2];
    __half* orow0 = ctx + ((size_t)b * SEQ + qr0) * DIM + h * HS;
    __half* orow1 = orow0 + (size_t)8 * DIM;
#pragma unroll
    for (int nt = 0; nt < 8; nt++) {
        int col = nt * 8 + 2 * tg;
        *(__half2*)(orow0 + col) =
            __float22half2_rn(make_float2(o[nt][0] * inv0, o[nt][1] * inv0));
        *(__half2*)(orow1 + col) =
            __float22half2_rn(make_float2(o[nt][2] * inv1, o[nt][3] * inv1));
    }
}

// ---------------------------------------------------------------------------
extern "C" void kernel_launch(void* const* d_in, const int* in_sizes, int n_in,
                              void* d_out, int out_size)
{
    const float* enc    = (const float*)d_in[0];
    const float* w_attn = (const float*)d_in[1];
    const float* b_attn = (const float*)d_in[2];
    const float* w_proj = (const float*)d_in[3];
    const float* b_proj = (const float*)d_in[4];
    float* out = (float*)d_out;

    __half *qkv = nullptr, *ctx = nullptr, *enc_h = nullptr,
           *wattn_h = nullptr, *wproj_h = nullptr;
    cudaGetSymbolAddress((void**)&qkv,     g_qkv);
    cudaGetSymbolAddress((void**)&ctx,     g_ctx);
    cudaGetSymbolAddress((void**)&enc_h,   g_enc_h);
    cudaGetSymbolAddress((void**)&wattn_h, g_wattn_h);
    cudaGetSymbolAddress((void**)&wproj_h, g_wproj_h);

    const int M = BATCH * SEQ;   // 8192

    // ---- pre-convert fp32 -> fp16 (single launch) ----
    cvt_all_kernel<<<(CVT_TOTAL + 255) / 256, 256>>>(
        (const float4*)enc, (const float4*)w_attn, (const float4*)w_proj,
        (uint2*)enc_h, (uint2*)wattn_h, (uint2*)wproj_h);

    cudaFuncSetAttribute(f16_gemm,
                         cudaFuncAttributeMaxDynamicSharedMemorySize, GEMM_SMEM);
    cudaFuncSetAttribute(attn_f16_kernel,
                         cudaFuncAttributeMaxDynamicSharedMemorySize, ATTN_SMEM);

    // ---- QKV GEMM (fp16 out) ----
    {
        dim3 grid(W3 / 128, M / 128);
        f16_gemm<<<grid, 256, GEMM_SMEM>>>(enc_h, wattn_h, b_attn, qkv,
                                           M, W3, DIM, 1);
    }

    // ---- Attention ----
    {
        dim3 grid(SEQ / 128, BATCH * HEADS);
        attn_f16_kernel<<<grid, 256, ATTN_SMEM>>>(qkv, ctx);
    }

    // ---- Output projection (fp32 out) ----
    {
        dim3 grid(DIM / 128, M / 128);
        f16_gemm<<<grid, 256, GEMM_SMEM>>>(ctx, wproj_h, b_proj, out,
                                           M, DIM, DIM, 0);
    }
}